// round 1
// baseline (speedup 1.0000x reference)
#include <cuda_runtime.h>
#include <math.h>

// Graph-LSTM: L=64, N=H=1024.
// Per step: ah = x_t @ h; i=sig(h@Whi+bi); f=sig(ah@Whf+bf); g=tanh(h@Whg+bg);
//           o=sig(ah@Who+bo); c = f*c + x_t@(i*g); h = o*tanh(c).
// out = [h0; h_1..h_64] (65*NH floats), then h_t, c_t if out_size allows.

#define NDIM 1024
#define NH   (NDIM * NDIM)
#define LSTEPS 64

// Scratch: ah, pre_i (later conv result), pre_f (later f), pre_g, pre_o (later o), ig, c
__device__ float g_scratch[7 * NH];

// ---------------------------------------------------------------------------
// SGEMM: C = A @ B, all [1024 x 1024] row-major fp32.
// 64x64 CTA tile, BK=16, 256 threads, 4x4 per-thread microtile.
// ---------------------------------------------------------------------------
__global__ __launch_bounds__(256) void sgemm_kernel(
    const float* __restrict__ A, const float* __restrict__ B,
    float* __restrict__ C)
{
    __shared__ float As[16][65];   // transposed A tile, padded (+1 avoids store conflicts)
    __shared__ float Bs[16][64];

    const int tid = threadIdx.x;
    const int bm  = blockIdx.y * 64;
    const int bn  = blockIdx.x * 64;

    // A-tile load mapping: 64 rows x 16 cols = 1024 floats = 256 float4
    const int arow = tid >> 2;          // 0..63
    const int acol = (tid & 3) * 4;     // 0,4,8,12
    // B-tile load mapping: 16 rows x 64 cols
    const int brow = tid >> 4;          // 0..15
    const int bcol = (tid & 15) * 4;    // 0..60
    // compute mapping
    const int tm = (tid >> 4) * 4;      // 0..60
    const int tn = (tid & 15) * 4;      // 0..60

    float acc[4][4] = {};

    const float* Aptr = A + (size_t)(bm + arow) * NDIM + acol;
    const float* Bptr = B + (size_t)brow * NDIM + bn + bcol;

    for (int k0 = 0; k0 < NDIM; k0 += 16) {
        float4 av = *(const float4*)(Aptr + k0);
        As[acol + 0][arow] = av.x;
        As[acol + 1][arow] = av.y;
        As[acol + 2][arow] = av.z;
        As[acol + 3][arow] = av.w;
        float4 bv = *(const float4*)(Bptr + (size_t)k0 * NDIM);
        *(float4*)&Bs[brow][bcol] = bv;
        __syncthreads();

        #pragma unroll
        for (int k = 0; k < 16; k++) {
            float a0 = As[k][tm + 0];
            float a1 = As[k][tm + 1];
            float a2 = As[k][tm + 2];
            float a3 = As[k][tm + 3];
            float b0 = Bs[k][tn + 0];
            float b1 = Bs[k][tn + 1];
            float b2 = Bs[k][tn + 2];
            float b3 = Bs[k][tn + 3];
            acc[0][0] += a0 * b0; acc[0][1] += a0 * b1; acc[0][2] += a0 * b2; acc[0][3] += a0 * b3;
            acc[1][0] += a1 * b0; acc[1][1] += a1 * b1; acc[1][2] += a1 * b2; acc[1][3] += a1 * b3;
            acc[2][0] += a2 * b0; acc[2][1] += a2 * b1; acc[2][2] += a2 * b2; acc[2][3] += a2 * b3;
            acc[3][0] += a3 * b0; acc[3][1] += a3 * b1; acc[3][2] += a3 * b2; acc[3][3] += a3 * b3;
        }
        __syncthreads();
    }

    #pragma unroll
    for (int i = 0; i < 4; i++) {
        float4 v = make_float4(acc[i][0], acc[i][1], acc[i][2], acc[i][3]);
        *(float4*)(C + (size_t)(bm + tm + i) * NDIM + bn + tn) = v;
    }
}

// ---------------------------------------------------------------------------
// Elementwise kernels
// ---------------------------------------------------------------------------
__device__ __forceinline__ float sigmoidf_(float x) {
    return 1.0f / (1.0f + expf(-x));
}

__global__ void init_kernel(float* __restrict__ out, float* __restrict__ c) {
    int idx = blockIdx.x * 256 + threadIdx.x;
    out[idx] = 0.0f;   // h0 = 0
    c[idx]   = 0.0f;   // c0 = 0
}

// pre_i/pre_f/pre_g/pre_o -> ig = i*g, f (in-place pf), o (in-place po)
__global__ void gates_kernel(
    const float* __restrict__ bi, const float* __restrict__ bf,
    const float* __restrict__ bg, const float* __restrict__ bo,
    const float* __restrict__ pi, float* __restrict__ pf,
    const float* __restrict__ pg, float* __restrict__ po,
    float* __restrict__ ig)
{
    int idx = blockIdx.x * 256 + threadIdx.x;
    int col = idx & (NDIM - 1);
    float iv = sigmoidf_(pi[idx] + bi[col]);
    float gv = tanhf(pg[idx] + bg[col]);
    ig[idx] = iv * gv;
    pf[idx] = sigmoidf_(pf[idx] + bf[col]);
    po[idx] = sigmoidf_(po[idx] + bo[col]);
}

// c = f*c + conv; h_next = o * tanh(c)
__global__ void cell_kernel(
    const float* __restrict__ f, const float* __restrict__ o,
    const float* __restrict__ conv, float* __restrict__ c,
    float* __restrict__ hout)
{
    int idx = blockIdx.x * 256 + threadIdx.x;
    float cv = f[idx] * c[idx] + conv[idx];
    c[idx] = cv;
    hout[idx] = o[idx] * tanhf(cv);
}

// out[65*NH + idx] = h_t ; out[66*NH + idx] = c_t
__global__ void tail_kernel(float* __restrict__ out, const float* __restrict__ c) {
    int idx = blockIdx.x * 256 + threadIdx.x;
    out[65 * (size_t)NH + idx] = out[64 * (size_t)NH + idx];
    out[66 * (size_t)NH + idx] = c[idx];
}

// ---------------------------------------------------------------------------
// Launcher
// ---------------------------------------------------------------------------
extern "C" void kernel_launch(void* const* d_in, const int* in_sizes, int n_in,
                              void* d_out, int out_size)
{
    const float* x   = (const float*)d_in[0];
    const float* Whi = (const float*)d_in[1];
    const float* bi  = (const float*)d_in[2];
    const float* Whf = (const float*)d_in[3];
    const float* bf  = (const float*)d_in[4];
    const float* Whg = (const float*)d_in[5];
    const float* bg  = (const float*)d_in[6];
    const float* Who = (const float*)d_in[7];
    const float* bo  = (const float*)d_in[8];
    float* out = (float*)d_out;

    float* s = nullptr;
    cudaGetSymbolAddress((void**)&s, g_scratch);
    float* ah = s + 0 * (size_t)NH;
    float* pi = s + 1 * (size_t)NH;   // pre_i, then reused as conv(x_t, ig)
    float* pf = s + 2 * (size_t)NH;   // pre_f, then f
    float* pg = s + 3 * (size_t)NH;
    float* po = s + 4 * (size_t)NH;   // pre_o, then o
    float* ig = s + 5 * (size_t)NH;
    float* c  = s + 6 * (size_t)NH;

    const dim3 gemm_grid(NDIM / 64, NDIM / 64);  // 16x16 = 256 CTAs
    const int  ew_grid = NH / 256;               // 4096 CTAs

    init_kernel<<<ew_grid, 256>>>(out, c);

    for (int t = 0; t < LSTEPS; t++) {
        const float* xt = x + (size_t)t * NH;
        const float* h  = out + (size_t)t * NH;
        float* hnext    = out + (size_t)(t + 1) * NH;

        // ah = x_t @ h
        sgemm_kernel<<<gemm_grid, 256>>>(xt, h, ah);
        // gate pre-activations (pi, pg depend only on h; pf, po on ah)
        sgemm_kernel<<<gemm_grid, 256>>>(h, Whi, pi);
        sgemm_kernel<<<gemm_grid, 256>>>(h, Whg, pg);
        sgemm_kernel<<<gemm_grid, 256>>>(ah, Whf, pf);
        sgemm_kernel<<<gemm_grid, 256>>>(ah, Who, po);
        // gates: ig = i*g, f->pf, o->po
        gates_kernel<<<ew_grid, 256>>>(bi, bf, bg, bo, pi, pf, pg, po, ig);
        // conv = x_t @ (i*g), stored into pi (pre_i no longer needed)
        sgemm_kernel<<<gemm_grid, 256>>>(xt, ig, pi);
        // c = f*c + conv ; h_next = o*tanh(c)
        cell_kernel<<<ew_grid, 256>>>(pf, po, pi, c, hnext);
    }

    // Append (h_t, c_t) if the output buffer carries the full pytree
    if (out_size >= 67 * NH) {
        tail_kernel<<<ew_grid, 256>>>(out, c);
    }
}

// round 3
// speedup vs baseline: 2.6097x; 2.6097x over previous
#include <cuda_runtime.h>
#include <math.h>
#include <stdint.h>

// Graph-LSTM: L=64, N=H=1024.
// Per step: ah = x_t @ h; [pi|pg] = h @ [Whi|Whg]; [pf|po] = ah @ [Whf|Who];
//           ig = sig(pi+bi)*tanh(pg+bg); f=sig(pf+bf); o=sig(po+bo);
//           c = f*c + x_t@ig; h = o*tanh(c).
// out = [h0; h_1..h_64], then h_t, c_t if out_size allows.

#define NDIM 1024
#define KDIM 1024
#define NH   (NDIM * NDIM)
#define LSTEPS 64

// Scratch: Wig(2) Wfo(2) ah(1) pig(2) pfo(2) ig(1) conv(1) cbuf(1) f(1) o(1) = 14 NH
__device__ float g_scratch[14 * NH];

__device__ __forceinline__ uint32_t f2tf(float f) {
    uint32_t r;
    asm("cvt.rna.tf32.f32 %0, %1;" : "=r"(r) : "f"(f));
    return r;
}

__device__ __forceinline__ void mma_tf32(float* c, const uint32_t* a, const uint32_t* b) {
    asm volatile(
        "mma.sync.aligned.m16n8k8.row.col.f32.tf32.tf32.f32 "
        "{%0,%1,%2,%3}, {%4,%5,%6,%7}, {%8,%9}, {%0,%1,%2,%3};"
        : "+f"(c[0]), "+f"(c[1]), "+f"(c[2]), "+f"(c[3])
        : "r"(a[0]), "r"(a[1]), "r"(a[2]), "r"(a[3]),
          "r"(b[0]), "r"(b[1]));
}

// ---------------------------------------------------------------------------
// TF32 GEMM: C[M=1024, N] = A[1024, 1024] @ B[1024, N], row-major.
// CTA tile 128x64, BK=16, 256 threads. Warp grid 4(M) x 2(N), warp tile 32x32.
// Double-buffered smem; pads chosen for conflict-free fragment loads.
// ---------------------------------------------------------------------------
__global__ __launch_bounds__(256) void tf32_gemm(
    const float* __restrict__ A, const float* __restrict__ B,
    float* __restrict__ C, int ldb, int ldc)
{
    __shared__ uint32_t As[2][128][20];  // [m][k], k-stride 20 -> conflict-free frag loads
    __shared__ uint32_t Bs[2][16][72];   // [k][n], n-stride 72 -> conflict-free frag loads

    const int tid  = threadIdx.x;
    const int lane = tid & 31;
    const int wid  = tid >> 5;
    const int wm   = (wid & 3) * 32;   // warp row offset in CTA tile
    const int wn   = (wid >> 2) * 32;  // warp col offset
    const int bm   = blockIdx.y * 128;
    const int bn   = blockIdx.x * 64;

    // global->smem load mapping
    const int ar  = tid >> 2;          // 0..63 (also +64)
    const int ak  = (tid & 3) * 4;     // 0,4,8,12
    const int bk  = tid >> 4;          // 0..15
    const int bn4 = (tid & 15) * 4;    // 0..60

    const float* Ap0 = A + (size_t)(bm + ar) * KDIM + ak;
    const float* Ap1 = Ap0 + (size_t)64 * KDIM;
    const float* Bp  = B + (size_t)bk * ldb + bn + bn4;

    float acc[2][4][4];
    #pragma unroll
    for (int i = 0; i < 2; i++)
        #pragma unroll
        for (int j = 0; j < 4; j++)
            #pragma unroll
            for (int k = 0; k < 4; k++) acc[i][j][k] = 0.0f;

    // prefetch iter 0
    float4 a0v = *(const float4*)(Ap0);
    float4 a1v = *(const float4*)(Ap1);
    float4 bv  = *(const float4*)(Bp);

    int buf = 0;
    for (int k0 = 0; k0 < KDIM; k0 += 16) {
        // store staged regs -> smem (convert to tf32, round-to-nearest)
        As[buf][ar][ak + 0] = f2tf(a0v.x);
        As[buf][ar][ak + 1] = f2tf(a0v.y);
        As[buf][ar][ak + 2] = f2tf(a0v.z);
        As[buf][ar][ak + 3] = f2tf(a0v.w);
        As[buf][ar + 64][ak + 0] = f2tf(a1v.x);
        As[buf][ar + 64][ak + 1] = f2tf(a1v.y);
        As[buf][ar + 64][ak + 2] = f2tf(a1v.z);
        As[buf][ar + 64][ak + 3] = f2tf(a1v.w);
        Bs[buf][bk][bn4 + 0] = f2tf(bv.x);
        Bs[buf][bk][bn4 + 1] = f2tf(bv.y);
        Bs[buf][bk][bn4 + 2] = f2tf(bv.z);
        Bs[buf][bk][bn4 + 3] = f2tf(bv.w);
        __syncthreads();

        if (k0 + 16 < KDIM) {
            a0v = *(const float4*)(Ap0 + k0 + 16);
            a1v = *(const float4*)(Ap1 + k0 + 16);
            bv  = *(const float4*)(Bp + (size_t)(k0 + 16) * ldb);
        }

        const int g  = lane >> 2;
        const int kq = lane & 3;
        #pragma unroll
        for (int ks = 0; ks < 16; ks += 8) {
            uint32_t af[2][4];
            uint32_t bf[4][2];
            #pragma unroll
            for (int im = 0; im < 2; im++) {
                const int row = wm + im * 16 + g;
                af[im][0] = As[buf][row][ks + kq];
                af[im][1] = As[buf][row + 8][ks + kq];
                af[im][2] = As[buf][row][ks + kq + 4];
                af[im][3] = As[buf][row + 8][ks + kq + 4];
            }
            #pragma unroll
            for (int in = 0; in < 4; in++) {
                const int col = wn + in * 8 + g;
                bf[in][0] = Bs[buf][ks + kq][col];
                bf[in][1] = Bs[buf][ks + kq + 4][col];
            }
            #pragma unroll
            for (int im = 0; im < 2; im++)
                #pragma unroll
                for (int in = 0; in < 4; in++)
                    mma_tf32(acc[im][in], af[im], bf[in]);
        }
        buf ^= 1;
    }

    // writeback
    #pragma unroll
    for (int im = 0; im < 2; im++) {
        #pragma unroll
        for (int in = 0; in < 4; in++) {
            const int row = bm + wm + im * 16 + (lane >> 2);
            const int col = bn + wn + in * 8 + (lane & 3) * 2;
            float2 v01 = make_float2(acc[im][in][0], acc[im][in][1]);
            float2 v23 = make_float2(acc[im][in][2], acc[im][in][3]);
            *(float2*)(C + (size_t)row * ldc + col)       = v01;
            *(float2*)(C + (size_t)(row + 8) * ldc + col) = v23;
        }
    }
}

// ---------------------------------------------------------------------------
// Elementwise kernels
// ---------------------------------------------------------------------------
__device__ __forceinline__ float sigmoidf_(float x) {
    return 1.0f / (1.0f + expf(-x));
}

__global__ void pack_kernel(
    const float* __restrict__ Whi, const float* __restrict__ Whg,
    const float* __restrict__ Whf, const float* __restrict__ Who,
    float* __restrict__ Wig, float* __restrict__ Wfo)
{
    int idx = blockIdx.x * 256 + threadIdx.x;
    int r = idx >> 10, c = idx & 1023;
    size_t o = (size_t)r * 2048 + c;
    Wig[o]        = Whi[idx];
    Wig[o + 1024] = Whg[idx];
    Wfo[o]        = Whf[idx];
    Wfo[o + 1024] = Who[idx];
}

__global__ void init_kernel(float* __restrict__ out, float* __restrict__ c) {
    int idx = blockIdx.x * 256 + threadIdx.x;
    out[idx] = 0.0f;
    c[idx]   = 0.0f;
}

__global__ void gates_kernel(
    const float* __restrict__ bi, const float* __restrict__ bf,
    const float* __restrict__ bg, const float* __restrict__ bo,
    const float* __restrict__ pig, const float* __restrict__ pfo,
    float* __restrict__ ig, float* __restrict__ fv, float* __restrict__ ov)
{
    int idx = blockIdx.x * 256 + threadIdx.x;
    int r = idx >> 10, c = idx & 1023;
    size_t o2 = (size_t)r * 2048 + c;
    float iv = sigmoidf_(pig[o2] + bi[c]);
    float gv = tanhf(pig[o2 + 1024] + bg[c]);
    ig[idx] = iv * gv;
    fv[idx] = sigmoidf_(pfo[o2] + bf[c]);
    ov[idx] = sigmoidf_(pfo[o2 + 1024] + bo[c]);
}

__global__ void cell_kernel(
    const float* __restrict__ f, const float* __restrict__ o,
    const float* __restrict__ conv, float* __restrict__ c,
    float* __restrict__ hout)
{
    int idx = blockIdx.x * 256 + threadIdx.x;
    float cv = f[idx] * c[idx] + conv[idx];
    c[idx] = cv;
    hout[idx] = o[idx] * tanhf(cv);
}

__global__ void tail_kernel(float* __restrict__ out, const float* __restrict__ c) {
    int idx = blockIdx.x * 256 + threadIdx.x;
    out[65 * (size_t)NH + idx] = out[64 * (size_t)NH + idx];
    out[66 * (size_t)NH + idx] = c[idx];
}

// ---------------------------------------------------------------------------
// Launcher
// ---------------------------------------------------------------------------
extern "C" void kernel_launch(void* const* d_in, const int* in_sizes, int n_in,
                              void* d_out, int out_size)
{
    const float* x   = (const float*)d_in[0];
    const float* Whi = (const float*)d_in[1];
    const float* bi  = (const float*)d_in[2];
    const float* Whf = (const float*)d_in[3];
    const float* bf  = (const float*)d_in[4];
    const float* Whg = (const float*)d_in[5];
    const float* bg  = (const float*)d_in[6];
    const float* Who = (const float*)d_in[7];
    const float* bo  = (const float*)d_in[8];
    float* out = (float*)d_out;

    static float* s = nullptr;
    if (!s) {
        cudaGetSymbolAddress((void**)&s, g_scratch);
    }
    float* Wig  = s + 0  * (size_t)NH;  // 1024 x 2048
    float* Wfo  = s + 2  * (size_t)NH;  // 1024 x 2048
    float* ah   = s + 4  * (size_t)NH;
    float* pig  = s + 5  * (size_t)NH;  // 1024 x 2048
    float* pfo  = s + 7  * (size_t)NH;  // 1024 x 2048
    float* ig   = s + 9  * (size_t)NH;
    float* conv = s + 10 * (size_t)NH;
    float* cbuf = s + 11 * (size_t)NH;
    float* fbuf = s + 12 * (size_t)NH;
    float* obuf = s + 13 * (size_t)NH;

    const int ew_grid = NH / 256;
    const dim3 g1(NDIM / 64, NDIM / 128);      // 16 x 8  = 128 CTAs (N=1024)
    const dim3 g2(2 * NDIM / 64, NDIM / 128);  // 32 x 8  = 256 CTAs (N=2048)

    pack_kernel<<<ew_grid, 256>>>(Whi, Whg, Whf, Who, Wig, Wfo);
    init_kernel<<<ew_grid, 256>>>(out, cbuf);

    for (int t = 0; t < LSTEPS; t++) {
        const float* xt = x + (size_t)t * NH;
        const float* h  = out + (size_t)t * NH;
        float* hnext    = out + (size_t)(t + 1) * NH;

        // ah = x_t @ h
        tf32_gemm<<<g1, 256>>>(xt, h, ah, NDIM, NDIM);
        // [pi|pg] = h @ [Whi|Whg]
        tf32_gemm<<<g2, 256>>>(h, Wig, pig, 2048, 2048);
        // [pf|po] = ah @ [Whf|Who]
        tf32_gemm<<<g2, 256>>>(ah, Wfo, pfo, 2048, 2048);
        // gates
        gates_kernel<<<ew_grid, 256>>>(bi, bf, bg, bo, pig, pfo, ig, fbuf, obuf);
        // conv = x_t @ ig
        tf32_gemm<<<g1, 256>>>(xt, ig, conv, NDIM, NDIM);
        // c = f*c + conv ; h_next = o*tanh(c)
        cell_kernel<<<ew_grid, 256>>>(fbuf, obuf, conv, cbuf, hnext);
    }

    if (out_size >= 67 * NH) {
        tail_kernel<<<ew_grid, 256>>>(out, cbuf);
    }
}